// round 16
// baseline (speedup 1.0000x reference)
#include <cuda_runtime.h>
#include <cuda_fp16.h>
#include <cstdint>

// out[b,s,t] = sum_k x[b, t+k-271] * W[s,k];  B=128, T=4096, S=64, K=543.
// fp16 mma.sync.m16n8k16 implicit GEMM, fp32 accum, 5-sigma support skip.
// 1 CTA/SM + 255-reg budget + explicit 2-stage software pipeline of W/a frags.

#define T_DIM   4096
#define S_DIM   64
#define K_DIM   543
#define NSTEP   34
#define WROW    552
#define TT      128
#define WIN     672
#define XROW    688

#define NCTA    148
#define NTILE   2048
#define MAXIT   14            // ceil(2048/148)

#define WS_BYTES   (64 * WROW * 2)                       // 70656
#define X_OFF      WS_BYTES
#define XBUF_E     (2 * 2 * XROW)
#define SMEM_BYTES (WS_BYTES + 2 * XBUF_E * 2)           // 81664

#define JSTRIDE    (8 * WROW * 2)                        // 8832 B per j-tile

__device__ uint16_t g_W[64][WROW];

__global__ void prep_bank(const float* __restrict__ W) {
    int idx = blockIdx.x * blockDim.x + threadIdx.x;
    if (idx >= 64 * WROW) return;
    int s  = idx / WROW;
    int kk = idx % WROW;
    float w = (kk < K_DIM) ? W[s * K_DIM + kk] : 0.0f;
    __half h = __float2half_rn(w);
    g_W[s][kk] = *reinterpret_cast<uint16_t*>(&h);
}

__device__ __forceinline__ uint32_t smem_u32(const void* p) {
    uint32_t a;
    asm("{ .reg .u64 t; cvta.to.shared.u64 t, %1; cvt.u32.u64 %0, t; }" : "=r"(a) : "l"(p));
    return a;
}
__device__ __forceinline__ uint32_t lds32(uint32_t a) {
    uint32_t v; asm volatile("ld.shared.b32 %0, [%1];" : "=r"(v) : "r"(a)); return v;
}
__device__ __forceinline__ void ldsm_x4(uint32_t& r0, uint32_t& r1,
                                        uint32_t& r2, uint32_t& r3, uint32_t a) {
    asm volatile("ldmatrix.sync.aligned.m8n8.x4.shared.b16 {%0,%1,%2,%3}, [%4];"
                 : "=r"(r0), "=r"(r1), "=r"(r2), "=r"(r3) : "r"(a));
}
__device__ __forceinline__ void ldsm_x2(uint32_t& r0, uint32_t& r1, uint32_t a) {
    asm volatile("ldmatrix.sync.aligned.m8n8.x2.shared.b16 {%0,%1}, [%2];"
                 : "=r"(r0), "=r"(r1) : "r"(a));
}
__device__ __forceinline__ void mma16816(float* c, uint32_t a0, uint32_t a1,
                                         uint32_t a2, uint32_t a3,
                                         uint32_t b0, uint32_t b1) {
    asm volatile(
        "mma.sync.aligned.m16n8k16.row.col.f32.f16.f16.f32 "
        "{%0,%1,%2,%3}, {%4,%5,%6,%7}, {%8,%9}, {%0,%1,%2,%3};"
        : "+f"(c[0]), "+f"(c[1]), "+f"(c[2]), "+f"(c[3])
        : "r"(a0), "r"(a1), "r"(a2), "r"(a3), "r"(b0), "r"(b1));
}

// 5-sigma support: lo_j = {15,14,12,10,6,0,0,0}; j active iff lo_j<=st<=33-lo_j
__device__ __forceinline__ constexpr int jstart(int st) {
    constexpr int tab[NSTEP] = {5,5,5,5,5,5, 4,4,4,4, 3,3, 2,2, 1, 0,0,0,0,
                                1, 2,2, 3,3, 4,4,4,4, 5,5,5,5,5,5};
    return tab[st];
}

extern __shared__ char smem_raw[];

__global__ __launch_bounds__(256, 1)
void cwt_mma_kernel(const float* __restrict__ x, float* __restrict__ out) {
    uint16_t* Wsm = reinterpret_cast<uint16_t*>(smem_raw);
    uint16_t* Xsm = reinterpret_cast<uint16_t*>(smem_raw + X_OFF);

    const int tid  = threadIdx.x;
    const int wid  = tid >> 5;
    const int lane = tid & 31;

    // ---- stage W once per CTA (== once per SM) ----
    {
        const int4* src = reinterpret_cast<const int4*>(&g_W[0][0]);
        int4* dst = reinterpret_cast<int4*>(Wsm);
        for (int i = tid; i < WS_BYTES / 16; i += 256) dst[i] = src[i];
    }

    // ---- fragment address constants ----
    const int g    = lane >> 2;
    const int q    = lane & 3;
    const int podd = g & 1;
    const int eb   = 16 * wid + g + 2 * q - podd;
    uint32_t xa[2][2];
    #pragma unroll
    for (int bf = 0; bf < 2; ++bf)
        #pragma unroll
        for (int bb = 0; bb < 2; ++bb)
            xa[bf][bb] = smem_u32(Xsm) +
                (uint32_t)((((bf * 2 + bb) * 2 + podd) * XROW + eb) * 2);
    const uint32_t wmbase = smem_u32(Wsm) +
        (uint32_t)((lane & 7) * (WROW * 2) + ((lane >> 3) & 1) * 16 +
                   (lane >> 4) * JSTRIDE);

    // ---- prologue: prefetch + stage tile 0 into buffer 0 ----
    float pre[2][3];
    {
        const int tile = blockIdx.x;
        const int bp = tile >> 5, t0 = (tile & 31) << 7;
        #pragma unroll
        for (int bb = 0; bb < 2; ++bb) {
            const float* xr = x + (size_t)(bp * 2 + bb) * T_DIM;
            #pragma unroll
            for (int r = 0; r < 3; ++r) {
                int i = tid + 256 * r;
                int gg = t0 + i - 271;
                pre[bb][r] = (i < WIN && gg >= 0 && gg < T_DIM) ? xr[gg] : 0.0f;
            }
        }
        #pragma unroll
        for (int bb = 0; bb < 2; ++bb) {
            uint16_t* p = Xsm + bb * 2 * XROW;
            #pragma unroll
            for (int r = 0; r < 3; ++r) {
                int i = tid + 256 * r;
                if (i < WIN) {
                    __half h = __float2half_rn(pre[bb][r]);
                    uint16_t hb = *reinterpret_cast<uint16_t*>(&h);
                    p[i] = hb;
                    if (i) p[XROW + i - 1] = hb;
                }
            }
        }
    }
    __syncthreads();

    for (int it = 0; it < MAXIT; ++it) {
        const int tile = blockIdx.x + NCTA * it;
        if (tile >= NTILE) break;
        const int bp = tile >> 5;
        const int t0 = (tile & 31) << 7;
        const int ntile = tile + NCTA;
        const bool have_next = (ntile < NTILE);

        // ---- prefetch next tile's x ----
        if (have_next) {
            const int nbp = ntile >> 5, nt0 = (ntile & 31) << 7;
            #pragma unroll
            for (int bb = 0; bb < 2; ++bb) {
                const float* xr = x + (size_t)(nbp * 2 + bb) * T_DIM;
                #pragma unroll
                for (int r = 0; r < 3; ++r) {
                    int i = tid + 256 * r;
                    int gg = nt0 + i - 271;
                    pre[bb][r] = (i < WIN && gg >= 0 && gg < T_DIM) ? xr[gg] : 0.0f;
                }
            }
        }

        const uint32_t xc0 = xa[it & 1][0];
        const uint32_t xc1 = xa[it & 1][1];

        float acc[2][8][4];
        #pragma unroll
        for (int bb = 0; bb < 2; ++bb)
            #pragma unroll
            for (int j = 0; j < 8; ++j)
                #pragma unroll
                for (int r = 0; r < 4; ++r) acc[bb][j][r] = 0.0f;

        // ---- software-pipelined mainloop: stage st+1 loads before st MMAs ----
        uint32_t wf[2][8][2];          // [pipe buf][j][frag]
        uint32_t a1r[2][2], a3r[2][2]; // [pipe buf][bb]
        uint32_t a0c[2];               // Hankel chain: a0(st+1) == a3(st)

        // preload st = 0
        {
            const int j0 = jstart(0);
            const uint32_t wst = wmbase;
            int j = j0;
            if (((8 - j0) & 1)) { ldsm_x2(wf[0][j][0], wf[0][j][1], wst + (uint32_t)(j * JSTRIDE)); ++j; }
            #pragma unroll
            for (int jj = 0; jj < 4; ++jj) {
                int jp = j + 2 * jj;
                if (jp >= 8) break;
                ldsm_x4(wf[0][jp][0], wf[0][jp][1], wf[0][jp + 1][0], wf[0][jp + 1][1],
                        wst + (uint32_t)(jp * JSTRIDE));
            }
            a0c[0] = lds32(xc0);        a0c[1] = lds32(xc1);
            a1r[0][0] = lds32(xc0 + 16); a1r[0][1] = lds32(xc1 + 16);
            a3r[0][0] = lds32(xc0 + 32); a3r[0][1] = lds32(xc1 + 32);
        }

        #pragma unroll
        for (int st = 0; st < NSTEP; ++st) {
            const int cb = st & 1;
            const int nb = cb ^ 1;
            // stage loads for st+1
            if (st + 1 < NSTEP) {
                const int j0n = jstart(st + 1);
                const uint32_t wst = wmbase + (uint32_t)((st + 1) * 32);
                int j = j0n;
                if (((8 - j0n) & 1)) { ldsm_x2(wf[nb][j][0], wf[nb][j][1], wst + (uint32_t)(j * JSTRIDE)); ++j; }
                #pragma unroll
                for (int jj = 0; jj < 4; ++jj) {
                    int jp = j + 2 * jj;
                    if (jp >= 8) break;
                    ldsm_x4(wf[nb][jp][0], wf[nb][jp][1], wf[nb][jp + 1][0], wf[nb][jp + 1][1],
                            wst + (uint32_t)(jp * JSTRIDE));
                }
                const uint32_t xo1 = (uint32_t)((st + 1) * 32);
                a1r[nb][0] = lds32(xc0 + xo1 + 16); a1r[nb][1] = lds32(xc1 + xo1 + 16);
                a3r[nb][0] = lds32(xc0 + xo1 + 32); a3r[nb][1] = lds32(xc1 + xo1 + 32);
            }
            // MMAs for st
            const int j0 = jstart(st);
            #pragma unroll
            for (int bb = 0; bb < 2; ++bb) {
                const uint32_t a0 = a0c[bb];
                const uint32_t a1 = a1r[cb][bb];
                const uint32_t a3 = a3r[cb][bb];
                a0c[bb] = a3;
                #pragma unroll
                for (int j = 0; j < 8; ++j) {
                    if (j < j0) continue;
                    mma16816(acc[bb][j], a0, a1, a1, a3, wf[cb][j][0], wf[cb][j][1]);
                }
            }
        }

        // ---- direct global stores ----
        const int tg = t0 + 16 * wid + g;
        #pragma unroll
        for (int bb = 0; bb < 2; ++bb) {
            float* ob = out + ((size_t)((bp * 2 + bb) * S_DIM)) * T_DIM;
            #pragma unroll
            for (int j = 0; j < 8; ++j) {
                float* r0 = ob + (size_t)(8 * j + 2 * q) * T_DIM + tg;
                float* r1 = r0 + T_DIM;
                r0[0] = acc[bb][j][0];
                r1[0] = acc[bb][j][1];
                r0[8] = acc[bb][j][2];
                r1[8] = acc[bb][j][3];
            }
        }

        // ---- stage next tile into buffer (it+1)&1, one sync ----
        if (have_next) {
            uint16_t* base = Xsm + ((it + 1) & 1) * XBUF_E;
            #pragma unroll
            for (int bb = 0; bb < 2; ++bb) {
                uint16_t* p = base + bb * 2 * XROW;
                #pragma unroll
                for (int r = 0; r < 3; ++r) {
                    int i = tid + 256 * r;
                    if (i < WIN) {
                        __half h = __float2half_rn(pre[bb][r]);
                        uint16_t hb = *reinterpret_cast<uint16_t*>(&h);
                        p[i] = hb;
                        if (i) p[XROW + i - 1] = hb;
                    }
                }
            }
            __syncthreads();
        }
    }
}

extern "C" void kernel_launch(void* const* d_in, const int* in_sizes, int n_in,
                              void* d_out, int out_size) {
    const float* x = (const float*)d_in[0];   // [128, 4096]
    const float* W = (const float*)d_in[1];   // [64, 543]
    float* out = (float*)d_out;               // [128, 64, 4096]
    (void)in_sizes; (void)n_in; (void)out_size;

    prep_bank<<<(64 * WROW + 255) / 256, 256>>>(W);

    cudaFuncSetAttribute(cwt_mma_kernel,
                         cudaFuncAttributeMaxDynamicSharedMemorySize, SMEM_BYTES);
    cwt_mma_kernel<<<NCTA, 256, SMEM_BYTES>>>(x, out);
}

// round 17
// speedup vs baseline: 1.0366x; 1.0366x over previous
#include <cuda_runtime.h>
#include <cuda_fp16.h>
#include <cstdint>

// out[b,s,t] = sum_k x[b, t+k-271] * W[s,k];  B=128, T=4096, S=64, K=543.
// fp16 mma.sync.m16n8k16 implicit GEMM, fp32 accum, 5-sigma support skip.
// 4 batches/CTA (4x W-fragment reuse), 1 CTA/SM, 255-reg budget,
// persistent CTAs + double-buffered x windows + LDSM W-frags + Hankel a-chain.

#define T_DIM   4096
#define S_DIM   64
#define K_DIM   543
#define NSTEP   34
#define WROW    552
#define TT      128
#define WIN     672
#define XROW    688
#define NB      4

#define NCTA    148
#define NTILE   1024           // 32 t-tiles * 32 batch-quads
#define MAXIT   7              // ceil(1024/148)

#define WS_BYTES   (64 * WROW * 2)                       // 70656
#define X_OFF      WS_BYTES
#define XBUF_E     (NB * 2 * XROW)                       // 5504 elems / buffer
#define SMEM_BYTES (WS_BYTES + 2 * XBUF_E * 2)           // 92672

#define JSTRIDE    (8 * WROW * 2)                        // 8832 B per j-tile

__device__ uint16_t g_W[64][WROW];

__global__ void prep_bank(const float* __restrict__ W) {
    int idx = blockIdx.x * blockDim.x + threadIdx.x;
    if (idx >= 64 * WROW) return;
    int s  = idx / WROW;
    int kk = idx % WROW;
    float w = (kk < K_DIM) ? W[s * K_DIM + kk] : 0.0f;
    __half h = __float2half_rn(w);
    g_W[s][kk] = *reinterpret_cast<uint16_t*>(&h);
}

__device__ __forceinline__ uint32_t smem_u32(const void* p) {
    uint32_t a;
    asm("{ .reg .u64 t; cvta.to.shared.u64 t, %1; cvt.u32.u64 %0, t; }" : "=r"(a) : "l"(p));
    return a;
}
__device__ __forceinline__ uint32_t lds32(uint32_t a) {
    uint32_t v; asm volatile("ld.shared.b32 %0, [%1];" : "=r"(v) : "r"(a)); return v;
}
__device__ __forceinline__ void ldsm_x4(uint32_t& r0, uint32_t& r1,
                                        uint32_t& r2, uint32_t& r3, uint32_t a) {
    asm volatile("ldmatrix.sync.aligned.m8n8.x4.shared.b16 {%0,%1,%2,%3}, [%4];"
                 : "=r"(r0), "=r"(r1), "=r"(r2), "=r"(r3) : "r"(a));
}
__device__ __forceinline__ void ldsm_x2(uint32_t& r0, uint32_t& r1, uint32_t a) {
    asm volatile("ldmatrix.sync.aligned.m8n8.x2.shared.b16 {%0,%1}, [%2];"
                 : "=r"(r0), "=r"(r1) : "r"(a));
}
__device__ __forceinline__ void mma16816(float* c, uint32_t a0, uint32_t a1,
                                         uint32_t a2, uint32_t a3,
                                         uint32_t b0, uint32_t b1) {
    asm volatile(
        "mma.sync.aligned.m16n8k16.row.col.f32.f16.f16.f32 "
        "{%0,%1,%2,%3}, {%4,%5,%6,%7}, {%8,%9}, {%0,%1,%2,%3};"
        : "+f"(c[0]), "+f"(c[1]), "+f"(c[2]), "+f"(c[3])
        : "r"(a0), "r"(a1), "r"(a2), "r"(a3), "r"(b0), "r"(b1));
}

// 5-sigma support: lo_j = {15,14,12,10,6,0,0,0}; j active iff lo_j<=st<=33-lo_j
__device__ __forceinline__ constexpr int jstart(int st) {
    constexpr int tab[NSTEP] = {5,5,5,5,5,5, 4,4,4,4, 3,3, 2,2, 1, 0,0,0,0,
                                1, 2,2, 3,3, 4,4,4,4, 5,5,5,5,5,5};
    return tab[st];
}

extern __shared__ char smem_raw[];

__global__ __launch_bounds__(256, 1)
void cwt_mma_kernel(const float* __restrict__ x, float* __restrict__ out) {
    uint16_t* Wsm = reinterpret_cast<uint16_t*>(smem_raw);
    uint16_t* Xsm = reinterpret_cast<uint16_t*>(smem_raw + X_OFF);

    const int tid  = threadIdx.x;
    const int wid  = tid >> 5;
    const int lane = tid & 31;

    // ---- stage W once per CTA (== per SM) ----
    {
        const int4* src = reinterpret_cast<const int4*>(&g_W[0][0]);
        int4* dst = reinterpret_cast<int4*>(Wsm);
        for (int i = tid; i < WS_BYTES / 16; i += 256) dst[i] = src[i];
    }

    // ---- fragment address constants ----
    const int g    = lane >> 2;
    const int q    = lane & 3;
    const int podd = g & 1;
    const int eb   = 16 * wid + g + 2 * q - podd;
    uint32_t xa[2][NB];
    #pragma unroll
    for (int bf = 0; bf < 2; ++bf)
        #pragma unroll
        for (int bb = 0; bb < NB; ++bb)
            xa[bf][bb] = smem_u32(Xsm) +
                (uint32_t)(((bf * NB + bb) * 2 + podd) * XROW * 2 + eb * 2);
    const uint32_t wmbase = smem_u32(Wsm) +
        (uint32_t)((lane & 7) * (WROW * 2) + ((lane >> 3) & 1) * 16 +
                   (lane >> 4) * JSTRIDE);

    // ---- prologue: prefetch + stage tile 0 into buffer 0 ----
    float pre[NB][3];
    {
        const int tile = blockIdx.x;
        const int bq = tile >> 5, t0 = (tile & 31) << 7;
        #pragma unroll
        for (int bb = 0; bb < NB; ++bb) {
            const float* xr = x + (size_t)(bq * NB + bb) * T_DIM;
            #pragma unroll
            for (int r = 0; r < 3; ++r) {
                int i = tid + 256 * r;
                int gg = t0 + i - 271;
                pre[bb][r] = (i < WIN && gg >= 0 && gg < T_DIM) ? xr[gg] : 0.0f;
            }
        }
        #pragma unroll
        for (int bb = 0; bb < NB; ++bb) {
            uint16_t* p = Xsm + bb * 2 * XROW;
            #pragma unroll
            for (int r = 0; r < 3; ++r) {
                int i = tid + 256 * r;
                if (i < WIN) {
                    __half h = __float2half_rn(pre[bb][r]);
                    uint16_t hb = *reinterpret_cast<uint16_t*>(&h);
                    p[i] = hb;
                    if (i) p[XROW + i - 1] = hb;
                }
            }
        }
    }
    __syncthreads();

    for (int it = 0; it < MAXIT; ++it) {
        const int tile = blockIdx.x + NCTA * it;
        if (tile >= NTILE) break;
        const int bq = tile >> 5;
        const int t0 = (tile & 31) << 7;
        const int ntile = tile + NCTA;
        const bool have_next = (ntile < NTILE);

        // ---- prefetch next tile's x ----
        if (have_next) {
            const int nbq = ntile >> 5, nt0 = (ntile & 31) << 7;
            #pragma unroll
            for (int bb = 0; bb < NB; ++bb) {
                const float* xr = x + (size_t)(nbq * NB + bb) * T_DIM;
                #pragma unroll
                for (int r = 0; r < 3; ++r) {
                    int i = tid + 256 * r;
                    int gg = nt0 + i - 271;
                    pre[bb][r] = (i < WIN && gg >= 0 && gg < T_DIM) ? xr[gg] : 0.0f;
                }
            }
        }

        uint32_t xc[NB];
        #pragma unroll
        for (int bb = 0; bb < NB; ++bb) xc[bb] = xa[it & 1][bb];

        float acc[NB][8][4];
        #pragma unroll
        for (int bb = 0; bb < NB; ++bb)
            #pragma unroll
            for (int j = 0; j < 8; ++j)
                #pragma unroll
                for (int r = 0; r < 4; ++r) acc[bb][j][r] = 0.0f;

        // Hankel a-frag chain: a0(st+1) == a3(st)
        uint32_t a0c[NB];
        #pragma unroll
        for (int bb = 0; bb < NB; ++bb) a0c[bb] = lds32(xc[bb]);

        #pragma unroll
        for (int st = 0; st < NSTEP; ++st) {
            const int j0 = jstart(st);              // compile-time
            const uint32_t wst = wmbase + (uint32_t)(st * 32);
            uint32_t wf[8][2];
            {
                int j = j0;
                if (((8 - j0) & 1)) {               // odd count: lead with .x2
                    ldsm_x2(wf[j][0], wf[j][1], wst + (uint32_t)(j * JSTRIDE));
                    ++j;
                }
                #pragma unroll
                for (int jj = 0; jj < 4; ++jj) {    // remaining pairs
                    int jp = j + 2 * jj;
                    if (jp >= 8) break;
                    ldsm_x4(wf[jp][0], wf[jp][1], wf[jp + 1][0], wf[jp + 1][1],
                            wst + (uint32_t)(jp * JSTRIDE));
                }
            }
            const uint32_t xo = (uint32_t)(st * 32);
            #pragma unroll
            for (int bb = 0; bb < NB; ++bb) {
                const uint32_t bh = xc[bb] + xo;
                const uint32_t a0 = a0c[bb];
                const uint32_t a1 = lds32(bh + 16);
                const uint32_t a3 = lds32(bh + 32);
                a0c[bb] = a3;
                #pragma unroll
                for (int j = 0; j < 8; ++j) {
                    if (j < j0) continue;
                    mma16816(acc[bb][j], a0, a1, a1, a3, wf[j][0], wf[j][1]);
                }
            }
        }

        // ---- direct global stores ----
        const int tg = t0 + 16 * wid + g;
        #pragma unroll
        for (int bb = 0; bb < NB; ++bb) {
            float* ob = out + ((size_t)((bq * NB + bb) * S_DIM)) * T_DIM;
            #pragma unroll
            for (int j = 0; j < 8; ++j) {
                float* r0 = ob + (size_t)(8 * j + 2 * q) * T_DIM + tg;
                float* r1 = r0 + T_DIM;
                r0[0] = acc[bb][j][0];
                r1[0] = acc[bb][j][1];
                r0[8] = acc[bb][j][2];
                r1[8] = acc[bb][j][3];
            }
        }

        // ---- stage next tile into buffer (it+1)&1, one sync ----
        if (have_next) {
            uint16_t* base = Xsm + ((it + 1) & 1) * XBUF_E;
            #pragma unroll
            for (int bb = 0; bb < NB; ++bb) {
                uint16_t* p = base + bb * 2 * XROW;
                #pragma unroll
                for (int r = 0; r < 3; ++r) {
                    int i = tid + 256 * r;
                    if (i < WIN) {
                        __half h = __float2half_rn(pre[bb][r]);
                        uint16_t hb = *reinterpret_cast<uint16_t*>(&h);
                        p[i] = hb;
                        if (i) p[XROW + i - 1] = hb;
                    }
                }
            }
            __syncthreads();
        }
    }
}

extern "C" void kernel_launch(void* const* d_in, const int* in_sizes, int n_in,
                              void* d_out, int out_size) {
    const float* x = (const float*)d_in[0];   // [128, 4096]
    const float* W = (const float*)d_in[1];   // [64, 543]
    float* out = (float*)d_out;               // [128, 64, 4096]
    (void)in_sizes; (void)n_in; (void)out_size;

    prep_bank<<<(64 * WROW + 255) / 256, 256>>>(W);

    cudaFuncSetAttribute(cwt_mma_kernel,
                         cudaFuncAttributeMaxDynamicSharedMemorySize, SMEM_BYTES);
    cwt_mma_kernel<<<NCTA, 256, SMEM_BYTES>>>(x, out);
}